// round 1
// baseline (speedup 1.0000x reference)
#include <cuda_runtime.h>
#include <cstdint>
#include <cstddef>

#define NU 100000
#define NI 200000
#define BB 3
#define EE 1000000
#define DD 64

// Scratch accumulators (device globals: allocation-free per harness rules)
__device__ float g_uscr[(size_t)BB * NU * DD];   // 76.8 MB
__device__ float g_iscr[(size_t)BB * NI * DD];   // 153.6 MB

// ---------------------------------------------------------------------------
// Scatter: COO spmm  out[row] += val * dense[col]   (atomic v4 reductions)
// One warp handles 32 edges: coalesced metadata load, then 16 iterations of
// 2 edges each (16 lanes per edge, one red.global.add.v4.f32 per lane).
// ---------------------------------------------------------------------------
__global__ void __launch_bounds__(256) scatter_kernel(
    const float* __restrict__ vals,
    const int*   __restrict__ rows,
    const int*   __restrict__ cols,
    const float* __restrict__ dense,
    float*       __restrict__ out,
    int nE)
{
    int warp = (blockIdx.x * blockDim.x + threadIdx.x) >> 5;
    int lane = threadIdx.x & 31;
    int e = warp * 32 + lane;

    float v = 0.0f; int r = 0, c = 0;
    if (e < nE) { v = vals[e]; r = rows[e]; c = cols[e]; }   // tail: v=0 -> adds 0

    int half = lane >> 4;      // 0: edge 2i, 1: edge 2i+1
    int l4   = lane & 15;      // float4 index within the 64-float row

    #pragma unroll
    for (int i = 0; i < 16; i++) {
        int src = 2 * i + half;
        float vv = __shfl_sync(0xffffffffu, v, src);
        int   rr = __shfl_sync(0xffffffffu, r, src);
        int   cc = __shfl_sync(0xffffffffu, c, src);

        const float4* dp = reinterpret_cast<const float4*>(dense + (size_t)cc * DD) + l4;
        float4 d = __ldg(dp);
        float4 p;
        p.x = vv * d.x; p.y = vv * d.y; p.z = vv * d.z; p.w = vv * d.w;

        float* op = out + (size_t)rr * DD + (size_t)l4 * 4;
        asm volatile("red.global.add.v4.f32 [%0], {%1,%2,%3,%4};"
                     :: "l"(op), "f"(p.x), "f"(p.y), "f"(p.z), "f"(p.w)
                     : "memory");
    }
}

// ---------------------------------------------------------------------------
// GEMM + sigmoid + in-tile mean.
// Block tile: 32 rows x 3 behaviors x 64 cols.  256 threads.
// Thread (g = t>>5, c = t&31): rows {g, g+8, g+16, g+24}, cols {c, c+32},
// all 3 behaviors -> 24 fp32 accumulators. Mean over b computed in-register.
// x read as broadcast LDS.128 (4 k per load); W rows read lane-consecutive.
// ---------------------------------------------------------------------------
__device__ __forceinline__ float sigmoidf_(float x) {
    return 1.0f / (1.0f + __expf(-x));
}

#define F4_GET(v, kk) ((kk) == 0 ? (v).x : ((kk) == 1 ? (v).y : ((kk) == 2 ? (v).z : (v).w)))

__global__ void __launch_bounds__(256) gemm_sig(
    const float* __restrict__ scr,      // [3, N, 64]
    const float* __restrict__ W,        // [64, 64] row-major (k, col)
    float*       __restrict__ out_per,  // [3, N, 64]
    float*       __restrict__ out_mean, // [N, 64]
    int N)
{
    __shared__ float4 sX[3 * 32 * 16];  // [ (b*32+r) ][ k/4 ]   24 KB
    __shared__ float  sW[64 * 64];      // [k][col]              16 KB

    int t  = threadIdx.x;
    int n0 = blockIdx.x * 32;

    // Load x tile (96 rows of 64 floats) as float4
    const float4* scr4 = reinterpret_cast<const float4*>(scr);
    #pragma unroll
    for (int i = 0; i < 6; i++) {
        int u  = t + i * 256;          // 0..1535 float4s
        int rb = u >> 4;               // 0..95
        int kq = u & 15;
        int b  = rb >> 5;
        int r  = rb & 31;
        sX[u] = scr4[((size_t)b * N + n0 + r) * 16 + kq];
    }
    // Load W
    const float4* W4  = reinterpret_cast<const float4*>(W);
    float4*       sW4 = reinterpret_cast<float4*>(sW);
    #pragma unroll
    for (int i = 0; i < 4; i++) sW4[t + i * 256] = W4[t + i * 256];
    __syncthreads();

    int c = t & 31;
    int g = t >> 5;

    float acc[3][4][2];
    #pragma unroll
    for (int b = 0; b < 3; b++)
        #pragma unroll
        for (int i = 0; i < 4; i++) { acc[b][i][0] = 0.0f; acc[b][i][1] = 0.0f; }

    for (int k4 = 0; k4 < 16; k4++) {
        float4 xv[3][4];
        #pragma unroll
        for (int b = 0; b < 3; b++)
            #pragma unroll
            for (int i = 0; i < 4; i++)
                xv[b][i] = sX[(b * 32 + g + 8 * i) * 16 + k4];   // warp-broadcast

        #pragma unroll
        for (int kk = 0; kk < 4; kk++) {
            int k = k4 * 4 + kk;
            float w0 = sW[k * 64 + c];
            float w1 = sW[k * 64 + c + 32];
            #pragma unroll
            for (int b = 0; b < 3; b++)
                #pragma unroll
                for (int i = 0; i < 4; i++) {
                    float xk = F4_GET(xv[b][i], kk);
                    acc[b][i][0] = fmaf(xk, w0, acc[b][i][0]);
                    acc[b][i][1] = fmaf(xk, w1, acc[b][i][1]);
                }
        }
    }

    // Epilogue: sigmoid per behavior + sigmoid of mean (pre-activation mean)
    #pragma unroll
    for (int i = 0; i < 4; i++) {
        int row = n0 + g + 8 * i;
        #pragma unroll
        for (int c2 = 0; c2 < 2; c2++) {
            int col = c + 32 * c2;
            float m = 0.0f;
            #pragma unroll
            for (int b = 0; b < 3; b++) {
                float y = acc[b][i][c2];
                m += y;
                out_per[((size_t)b * N + row) * 64 + col] = sigmoidf_(y);
            }
            out_mean[(size_t)row * 64 + col] = sigmoidf_(m * (1.0f / 3.0f));
        }
    }
}

// ---------------------------------------------------------------------------
// Launch
// ---------------------------------------------------------------------------
extern "C" void kernel_launch(void* const* d_in, const int* in_sizes, int n_in,
                              void* d_out, int out_size)
{
    const float* user_emb = (const float*)d_in[0];
    const float* item_emb = (const float*)d_in[1];
    const float* u2i_vals = (const float*)d_in[2];
    const int*   u2i_rows = (const int*)  d_in[3];
    const int*   u2i_cols = (const int*)  d_in[4];
    const float* i2u_vals = (const float*)d_in[5];
    const int*   i2u_rows = (const int*)  d_in[6];
    const int*   i2u_cols = (const int*)  d_in[7];
    const float* u_w      = (const float*)d_in[8];
    const float* i_w      = (const float*)d_in[9];

    float* out     = (float*)d_out;
    float* out_ue  = out;                                              // [NU,64]
    float* out_ie  = out + (size_t)NU * DD;                            // [NI,64]
    float* out_ues = out + (size_t)(NU + NI) * DD;                     // [3,NU,64]
    float* out_ies = out + (size_t)(NU + NI) * DD + (size_t)BB * NU * DD; // [3,NI,64]

    void* uscr_v = nullptr; void* iscr_v = nullptr;
    cudaGetSymbolAddress(&uscr_v, g_uscr);
    cudaGetSymbolAddress(&iscr_v, g_iscr);
    float* uscr = (float*)uscr_v;
    float* iscr = (float*)iscr_v;

    cudaMemsetAsync(uscr, 0, sizeof(g_uscr), 0);
    cudaMemsetAsync(iscr, 0, sizeof(g_iscr), 0);

    int sblocks = (EE + 255) / 256;   // 256 edges per block (8 warps x 32)
    for (int b = 0; b < BB; b++) {
        scatter_kernel<<<sblocks, 256>>>(
            u2i_vals + (size_t)b * EE, u2i_rows + (size_t)b * EE,
            u2i_cols + (size_t)b * EE, item_emb,
            uscr + (size_t)b * NU * DD, EE);
        scatter_kernel<<<sblocks, 256>>>(
            i2u_vals + (size_t)b * EE, i2u_rows + (size_t)b * EE,
            i2u_cols + (size_t)b * EE, user_emb,
            iscr + (size_t)b * NI * DD, EE);
    }

    gemm_sig<<<NU / 32, 256>>>(uscr, u_w, out_ues, out_ue, NU);
    gemm_sig<<<NI / 32, 256>>>(iscr, i_w, out_ies, out_ie, NI);
}